// round 3
// baseline (speedup 1.0000x reference)
#include <cuda_runtime.h>

#define BB 8192
#define TT 256

typedef unsigned long long ull;

// Scratch (no allocations allowed): transposed x with one padded row for the
// branchless t+1 prefetch, plus per-lane repacked/sampled/pre-scaled weights.
__device__ float g_xT[(TT + 1) * BB];
// 8-lane layout: lane subq owns gate-type t=subq>>1 (i,f,g,o) x half hh=subq&1
// (gates 10t+5hh .. +5). Rows (j) permuted per lane: own-half h rows first.
// Columns padded 5->6 so the GEMM is 3 f32x2 pairs per row.
__device__ __align__(16) float g_whh8[8 * 10 * 6];
__device__ __align__(16) float g_wih8[8 * 6];
__device__ __align__(16) float g_bb8[8 * 6];

__device__ __forceinline__ float tanh_approx(float x) {
    float y; asm("tanh.approx.f32 %0, %1;" : "=f"(y) : "f"(x)); return y;
}
__device__ __forceinline__ ull pk2(float lo, float hi) {
    ull r; asm("mov.b64 %0, {%1, %2};" : "=l"(r) : "f"(lo), "f"(hi)); return r;
}
__device__ __forceinline__ void upk2(float& lo, float& hi, ull v) {
    asm("mov.b64 {%0, %1}, %2;" : "=f"(lo), "=f"(hi) : "l"(v));
}
__device__ __forceinline__ ull fma2(ull a, ull b, ull c) {
    ull d; asm("fma.rn.f32x2 %0, %1, %2, %3;" : "=l"(d) : "l"(a), "l"(b), "l"(c));
    return d;
}

// ---------------------------------------------------------------------------
// Setup: sample variational weights (w = mu + softplus(rho)*eps) and repack
// into the 8-lane layout with the sigmoid half-angle pre-scale folded in:
//   t in {0,1,3} (i,f,o -> sigmoid): S = 0.5  (sigmoid(z) = 0.5*tanh(z/2)+0.5)
//   t == 2      (g   -> tanh)     : S = 1.0
// ---------------------------------------------------------------------------
__global__ void setup_kernel(const float* __restrict__ wih_mu, const float* __restrict__ wih_rho,
                             const float* __restrict__ whh_mu, const float* __restrict__ whh_rho,
                             const float* __restrict__ b_mu,   const float* __restrict__ b_rho,
                             const float* __restrict__ eps_ih, const float* __restrict__ eps_hh,
                             const float* __restrict__ eps_b)
{
    int tid = threadIdx.x;
    for (int idx = tid; idx < 480; idx += blockDim.x) {
        int subq = idx / 60, rem = idx % 60, jj = rem / 6, cc = rem % 6;
        int t = subq >> 1, hh = subq & 1;
        float S = (t == 2) ? 1.f : 0.5f;
        float v = 0.f;
        if (cc < 5) {
            int j = (jj < 5) ? (5 * hh + jj) : (5 * (1 - hh) + (jj - 5));
            int gate = 10 * t + 5 * hh + cc;
            int wi = j * 40 + gate;
            float w = whh_mu[wi] + log1pf(expf(whh_rho[wi])) * eps_hh[wi];
            v = S * w;
        }
        g_whh8[subq * 60 + jj * 6 + cc] = v;
    }
    if (tid < 48) {
        int subq = tid / 6, cc = tid % 6;
        int t = subq >> 1, hh = subq & 1;
        float S = (t == 2) ? 1.f : 0.5f;
        float vi = 0.f, vb = 0.f;
        if (cc < 5) {
            int gate = 10 * t + 5 * hh + cc;
            vi = S * (wih_mu[gate] + log1pf(expf(wih_rho[gate])) * eps_ih[gate]);
            vb = S * (b_mu[gate]   + log1pf(expf(b_rho[gate]))   * eps_b[gate]);
        }
        g_wih8[subq * 6 + cc] = vi;
        g_bb8[subq * 6 + cc]  = vb;
    }
}

// ---------------------------------------------------------------------------
// Transpose x: (B, T) -> (T, B) so the hot loop reads one 32B sector / warp.
// ---------------------------------------------------------------------------
__global__ void transpose_kernel(const float* __restrict__ x)
{
    __shared__ float tile[32][33];
    int t0 = blockIdx.x * 32, b0 = blockIdx.y * 32;
    int tx = threadIdx.x, ty = threadIdx.y;
#pragma unroll
    for (int i = ty; i < 32; i += 8)
        tile[i][tx] = x[(size_t)(b0 + i) * TT + t0 + tx];
    __syncthreads();
#pragma unroll
    for (int i = ty; i < 32; i += 8)
        g_xT[(size_t)(t0 + i) * BB + b0 + tx] = tile[tx][i];
}

// Zero the padding row read by the branchless prefetch at t = T-1.
__global__ void pad_kernel()
{
    int i = blockIdx.x * blockDim.x + threadIdx.x;
    if (i < BB) g_xT[(size_t)TT * BB + i] = 0.f;
}

// ---------------------------------------------------------------------------
// Main recurrence. 8 lanes per batch element, 4 batches per warp, 2048 warps
// (13.8/SM). Lane subq owns 5 gates (type t = subq>>1, k-half hh = subq&1)
// and keeps its 30 padded w_hh pairs in registers; the recurrent GEMM is pure
// fma.rn.f32x2 (30 packed FMAs). The c/h update is distributed by k-half:
// each lane gathers i,f,g,o for its 5 k values via width-8 shuffles (roles
// live at lanes hh, 2+hh, 4+hh, 6+hh), updates c/h for its half, then swaps
// halves with lane subq^1 (5 shuffles). Weight rows are pre-permuted so the
// (own-half, other-half) h ordering needs no per-lane selects.
// ---------------------------------------------------------------------------
__global__ void __launch_bounds__(32)
lstm_kernel(const float* __restrict__ lin_w, const float* __restrict__ lin_b,
            float* __restrict__ out)
{
    int lane  = threadIdx.x;
    int subq  = lane & 7;
    int hh    = subq & 1;
    int batch = blockIdx.x * 4 + (lane >> 3);

    // One-time: this lane's weights as packed f32x2 (8B-aligned rows).
    ull w2[30], wih2[3], bb2[3];
    {
        const ull* wp = reinterpret_cast<const ull*>(g_whh8 + subq * 60);
#pragma unroll
        for (int i = 0; i < 30; i++) w2[i] = wp[i];
        const ull* ip = reinterpret_cast<const ull*>(g_wih8 + subq * 6);
        const ull* bp = reinterpret_cast<const ull*>(g_bb8  + subq * 6);
#pragma unroll
        for (int p = 0; p < 3; p++) { wih2[p] = ip[p]; bb2[p] = bp[p]; }
    }

    // act = fma(A, tanh(acc), D): sigmoid lanes A=0.5,D=0.5 ; g lanes A=1,D=0
    float A = ((subq >> 1) == 2) ? 1.f : 0.5f;
    float D = ((subq >> 1) == 2) ? 0.f : 0.5f;

    float c[5], hl[5], ho[5];
#pragma unroll
    for (int k = 0; k < 5; k++) { c[k] = 0.f; hl[k] = 0.f; ho[k] = 0.f; }

    const float* xp = g_xT + batch;
    float xv = xp[0];

#pragma unroll 1
    for (int t = 0; t < TT; t++) {
        xp += BB;
        float xn = *xp;  // prefetch next timestep (padded row at t = T-1)

        // gates: acc = S * (x*w_ih + b + h @ w_hh) for this lane's 5(+1 pad)
        ull xx = pk2(xv, xv);
        ull acc2[3];
#pragma unroll
        for (int p = 0; p < 3; p++) acc2[p] = fma2(xx, wih2[p], bb2[p]);
#pragma unroll
        for (int jj = 0; jj < 10; jj++) {
            float hj = (jj < 5) ? hl[jj] : ho[jj - 5];
            ull h2 = pk2(hj, hj);
#pragma unroll
            for (int p = 0; p < 3; p++) acc2[p] = fma2(h2, w2[jj * 3 + p], acc2[p]);
        }

        // activations: 1 MUFU tanh + 1 FMA per real gate (5)
        float act[5];
        {
            float a0, a1;
            upk2(a0, a1, acc2[0]);
            act[0] = fmaf(A, tanh_approx(a0), D);
            act[1] = fmaf(A, tanh_approx(a1), D);
            upk2(a0, a1, acc2[1]);
            act[2] = fmaf(A, tanh_approx(a0), D);
            act[3] = fmaf(A, tanh_approx(a1), D);
            upk2(a0, a1, acc2[2]);
            act[4] = fmaf(A, tanh_approx(a0), D);
        }

        // gather i,f,g,o for this lane's k-half; update c,h for that half
#pragma unroll
        for (int k = 0; k < 5; k++) {
            float iv = __shfl_sync(0xffffffffu, act[k], hh,     8);
            float fv = __shfl_sync(0xffffffffu, act[k], 2 + hh, 8);
            float gv = __shfl_sync(0xffffffffu, act[k], 4 + hh, 8);
            float ov = __shfl_sync(0xffffffffu, act[k], 6 + hh, 8);
            c[k]  = fmaf(fv, c[k], iv * gv);
            hl[k] = ov * tanh_approx(c[k]);
        }
        // swap halves: other-half h from the paired lane (same type, hh^1)
#pragma unroll
        for (int k = 0; k < 5; k++)
            ho[k] = __shfl_sync(0xffffffffu, hl[k], subq ^ 1, 8);

        xv = xn;
    }

    // linear head: out[b] = h . lin_w + lin_b  (lane subq==0: hl=h[0:5], ho=h[5:10])
    if (subq == 0) {
        float s = lin_b[0];
#pragma unroll
        for (int k = 0; k < 5; k++) s = fmaf(hl[k], lin_w[k], s);
#pragma unroll
        for (int k = 0; k < 5; k++) s = fmaf(ho[k], lin_w[5 + k], s);
        out[batch] = s;
    }
}

extern "C" void kernel_launch(void* const* d_in, const int* in_sizes, int n_in,
                              void* d_out, int out_size)
{
    const float* x       = (const float*)d_in[0];
    const float* wih_mu  = (const float*)d_in[1];
    const float* wih_rho = (const float*)d_in[2];
    const float* whh_mu  = (const float*)d_in[3];
    const float* whh_rho = (const float*)d_in[4];
    const float* b_mu    = (const float*)d_in[5];
    const float* b_rho   = (const float*)d_in[6];
    const float* eps_ih  = (const float*)d_in[7];
    const float* eps_hh  = (const float*)d_in[8];
    const float* eps_b   = (const float*)d_in[9];
    const float* lin_w   = (const float*)d_in[10];
    const float* lin_b   = (const float*)d_in[11];
    float* out = (float*)d_out;

    setup_kernel<<<1, 512>>>(wih_mu, wih_rho, whh_mu, whh_rho,
                             b_mu, b_rho, eps_ih, eps_hh, eps_b);
    transpose_kernel<<<dim3(TT / 32, BB / 32), dim3(32, 8)>>>(x);
    pad_kernel<<<BB / 256, 256>>>();
    lstm_kernel<<<BB / 4, 32>>>(lin_w, lin_b, out);
}

// round 4
// speedup vs baseline: 1.4877x; 1.4877x over previous
#include <cuda_runtime.h>

#define BB 8192
#define TT 256

typedef unsigned long long ull;

// Scratch (no allocations allowed): transposed x with one padded row for the
// branchless t+1 prefetch, plus per-lane repacked/sampled/pre-scaled weights.
__device__ float g_xT[(TT + 1) * BB];
// Quad2 layout: 4 lanes per batch. Lane q: tp = q&1 (type-pair: 0 -> {i,f},
// 1 -> {g,o}), hh = q>>1 (k-half). Lane owns 10 gates: cols c=0..9 with
// type = 2*tp + c/5, k = 5*hh + c%5. No padding.
__device__ __align__(16) float g_w4[4 * 10 * 10];  // [q][j][c]
__device__ __align__(16) float g_wih4[4 * 10];     // [q][c]
__device__ __align__(16) float g_bb4[4 * 10];      // [q][c]

__device__ __forceinline__ float tanh_approx(float x) {
    float y; asm("tanh.approx.f32 %0, %1;" : "=f"(y) : "f"(x)); return y;
}
__device__ __forceinline__ ull pk2(float lo, float hi) {
    ull r; asm("mov.b64 %0, {%1, %2};" : "=l"(r) : "f"(lo), "f"(hi)); return r;
}
__device__ __forceinline__ void upk2(float& lo, float& hi, ull v) {
    asm("mov.b64 {%0, %1}, %2;" : "=f"(lo), "=f"(hi) : "l"(v));
}
__device__ __forceinline__ ull fma2(ull a, ull b, ull c) {
    ull d; asm("fma.rn.f32x2 %0, %1, %2, %3;" : "=l"(d) : "l"(a), "l"(b), "l"(c));
    return d;
}

// ---------------------------------------------------------------------------
// Setup: sample variational weights (w = mu + softplus(rho)*eps) and repack
// into the Quad2 per-lane layout with the sigmoid half-angle pre-scale:
//   types 0,1,3 (i,f,o -> sigmoid): S = 0.5  (sigmoid(z) = 0.5*tanh(z/2)+0.5)
//   type  2     (g   -> tanh)     : S = 1.0
// ---------------------------------------------------------------------------
__global__ void setup_kernel(const float* __restrict__ wih_mu, const float* __restrict__ wih_rho,
                             const float* __restrict__ whh_mu, const float* __restrict__ whh_rho,
                             const float* __restrict__ b_mu,   const float* __restrict__ b_rho,
                             const float* __restrict__ eps_ih, const float* __restrict__ eps_hh,
                             const float* __restrict__ eps_b)
{
    int tid = threadIdx.x;
    for (int idx = tid; idx < 400; idx += blockDim.x) {
        int q = idx / 100, rem = idx % 100, j = rem / 10, c = rem % 10;
        int tp = q & 1, hh = (q >> 1) & 1;
        int type = 2 * tp + c / 5;
        int k = 5 * hh + c % 5;
        int gate = 10 * type + k;
        float S = (type == 2) ? 1.f : 0.5f;
        int wi = j * 40 + gate;
        float w = whh_mu[wi] + log1pf(expf(whh_rho[wi])) * eps_hh[wi];
        g_w4[q * 100 + j * 10 + c] = S * w;
    }
    if (tid < 40) {
        int q = tid / 10, c = tid % 10;
        int tp = q & 1, hh = (q >> 1) & 1;
        int type = 2 * tp + c / 5;
        int k = 5 * hh + c % 5;
        int gate = 10 * type + k;
        float S = (type == 2) ? 1.f : 0.5f;
        g_wih4[q * 10 + c] = S * (wih_mu[gate] + log1pf(expf(wih_rho[gate])) * eps_ih[gate]);
        g_bb4[q * 10 + c]  = S * (b_mu[gate]   + log1pf(expf(b_rho[gate]))   * eps_b[gate]);
    }
}

// ---------------------------------------------------------------------------
// Transpose x: (B, T) -> (T, B) so the hot loop reads one 32B sector / warp.
// ---------------------------------------------------------------------------
__global__ void transpose_kernel(const float* __restrict__ x)
{
    __shared__ float tile[32][33];
    int t0 = blockIdx.x * 32, b0 = blockIdx.y * 32;
    int tx = threadIdx.x, ty = threadIdx.y;
#pragma unroll
    for (int i = ty; i < 32; i += 8)
        tile[i][tx] = x[(size_t)(b0 + i) * TT + t0 + tx];
    __syncthreads();
#pragma unroll
    for (int i = ty; i < 32; i += 8)
        g_xT[(size_t)(t0 + i) * BB + b0 + tx] = tile[tx][i];
}

// Zero the padding row read by the branchless prefetch at t = T-1.
__global__ void pad_kernel()
{
    int i = blockIdx.x * blockDim.x + threadIdx.x;
    if (i < BB) g_xT[(size_t)TT * BB + i] = 0.f;
}

// ---------------------------------------------------------------------------
// Main recurrence (Quad2). 4 lanes per batch, 8 batches per warp, 1024 warps.
// Lane q (tp = q&1, hh = q>>1) computes 10 gates = types {2tp, 2tp+1} for
// k in [5hh, 5hh+5). GEMM: 55 fma.rn.f32x2, h[j] splats come via 10 shuffles
// from the half-owners (per-lane src = tp | (j>=5 ? 2 : 0)). One shfl_xor
// round (10) swaps acts with the partner lane so each lane holds i,f,g,o for
// its 5 k's; i*g is tp-symmetric, f/o picked by 2 SELs per k. Each lane then
// updates c,h for its own k-half only (2x redundancy instead of 4x).
// ---------------------------------------------------------------------------
__global__ void __launch_bounds__(32)
lstm_kernel(const float* __restrict__ lin_w, const float* __restrict__ lin_b,
            float* __restrict__ out)
{
    const unsigned FULL = 0xffffffffu;
    int lane  = threadIdx.x;
    int q     = lane & 3;
    int tp    = q & 1;
    int batch = blockIdx.x * 8 + (lane >> 2);

    // One-time: this lane's weights as packed f32x2 (rows are 40B, 8B-aligned).
    ull w2[50], wih2[5], bb2[5];
    {
        const ull* wp = reinterpret_cast<const ull*>(g_w4 + q * 100);
#pragma unroll
        for (int i = 0; i < 50; i++) w2[i] = wp[i];
        const ull* ip = reinterpret_cast<const ull*>(g_wih4 + q * 10);
        const ull* bp = reinterpret_cast<const ull*>(g_bb4  + q * 10);
#pragma unroll
        for (int p = 0; p < 5; p++) { wih2[p] = ip[p]; bb2[p] = bp[p]; }
    }

    // act for cols 0..4 (type 2tp): tp=0 -> sigmoid(0.5,0.5), tp=1 -> tanh(1,0)
    // act for cols 5..9 (type 2tp+1): always sigmoid (f or o)
    float A_lo = tp ? 1.f : 0.5f;
    float D_lo = tp ? 0.f : 0.5f;

    // h-broadcast sources: h[j] (j<5) lives on lanes with hh=0, (j>=5) hh=1;
    // read from the same-tp owner.
    int s0 = tp, s1 = tp | 2;

    float c[5], hl[5];
#pragma unroll
    for (int m = 0; m < 5; m++) { c[m] = 0.f; hl[m] = 0.f; }

    const float* xp = g_xT + batch;
    float xv = xp[0];

#pragma unroll 1
    for (int t = 0; t < TT; t++) {
        xp += BB;
        float xn = *xp;  // prefetch next timestep (padded row at t = T-1)

        // gates: acc = S * (x*w_ih + b + h @ w_hh), 10 cols as 5 f32x2
        ull xx = pk2(xv, xv);
        ull acc2[5];
#pragma unroll
        for (int p = 0; p < 5; p++) acc2[p] = fma2(xx, wih2[p], bb2[p]);
#pragma unroll
        for (int j = 0; j < 10; j++) {
            float hj = __shfl_sync(FULL, hl[j % 5], (j < 5) ? s0 : s1, 4);
            ull h2 = pk2(hj, hj);
#pragma unroll
            for (int p = 0; p < 5; p++) acc2[p] = fma2(h2, w2[j * 5 + p], acc2[p]);
        }

        // activations: 1 MUFU tanh + 1 FMA per gate
        float act[10];
#pragma unroll
        for (int p = 0; p < 5; p++) {
            float a0, a1; upk2(a0, a1, acc2[p]);
            if (p < 2) {            // cols 0,1,2,3: type 2tp
                act[2 * p]     = fmaf(A_lo, tanh_approx(a0), D_lo);
                act[2 * p + 1] = fmaf(A_lo, tanh_approx(a1), D_lo);
            } else if (p == 2) {    // col 4: type 2tp, col 5: type 2tp+1
                act[4] = fmaf(A_lo, tanh_approx(a0), D_lo);
                act[5] = fmaf(0.5f, tanh_approx(a1), 0.5f);
            } else {                // cols 6..9: type 2tp+1 (sigmoid)
                act[2 * p]     = fmaf(0.5f, tanh_approx(a0), 0.5f);
                act[2 * p + 1] = fmaf(0.5f, tanh_approx(a1), 0.5f);
            }
        }

        // swap acts with the partner lane (other type-pair, same k-half)
        float recv[10];
#pragma unroll
        for (int k = 0; k < 10; k++)
            recv[k] = __shfl_xor_sync(FULL, act[k], 1, 4);

        // update c,h for this lane's k-half:
        //   i*g = act_lo * recv_lo (tp-symmetric); f,o picked by tp
#pragma unroll
        for (int m = 0; m < 5; m++) {
            float ig = act[m] * recv[m];
            float fv = tp ? recv[5 + m] : act[5 + m];
            float ov = tp ? act[5 + m]  : recv[5 + m];
            c[m]  = fmaf(fv, c[m], ig);
            hl[m] = ov * tanh_approx(c[m]);
        }
        xv = xn;
    }

    // linear head: out[b] = h . lin_w + lin_b (all lanes compute, q==0 stores)
    float s = lin_b[0];
#pragma unroll
    for (int j = 0; j < 10; j++) {
        float hv = __shfl_sync(FULL, hl[j % 5], (j < 5) ? s0 : s1, 4);
        s = fmaf(hv, lin_w[j], s);
    }
    if (q == 0) out[batch] = s;
}

extern "C" void kernel_launch(void* const* d_in, const int* in_sizes, int n_in,
                              void* d_out, int out_size)
{
    const float* x       = (const float*)d_in[0];
    const float* wih_mu  = (const float*)d_in[1];
    const float* wih_rho = (const float*)d_in[2];
    const float* whh_mu  = (const float*)d_in[3];
    const float* whh_rho = (const float*)d_in[4];
    const float* b_mu    = (const float*)d_in[5];
    const float* b_rho   = (const float*)d_in[6];
    const float* eps_ih  = (const float*)d_in[7];
    const float* eps_hh  = (const float*)d_in[8];
    const float* eps_b   = (const float*)d_in[9];
    const float* lin_w   = (const float*)d_in[10];
    const float* lin_b   = (const float*)d_in[11];
    float* out = (float*)d_out;

    setup_kernel<<<1, 512>>>(wih_mu, wih_rho, whh_mu, whh_rho,
                             b_mu, b_rho, eps_ih, eps_hh, eps_b);
    transpose_kernel<<<dim3(TT / 32, BB / 32), dim3(32, 8)>>>(x);
    pad_kernel<<<BB / 256, 256>>>();
    lstm_kernel<<<BB / 8, 32>>>(lin_w, lin_b, out);
}